// round 12
// baseline (speedup 1.0000x reference)
#include <cuda_runtime.h>
#include <cuda_bf16.h>
#include <cstdint>

// BG_LSTM via warp-level HMMA, R12: A-in-registers + DSMEM h exchange.
// 16 clusters x 16 CTAs (non-portable), 128 thr/CTA, 2 CTAs/SM.
// Cluster owns 32 batches; rank owns 16 units (64 gate rows).
// W_hh lives in REGISTERS as bf16 hi/lo mma fragments (loaded once from
// global; no SMEM W, no A-ldmatrix). B (h planes, bf16 hi/lo) is double-
// buffered in SMEM and written DIRECTLY by peer CTAs via st.shared::cluster
// (no global h buffer, no LDG staging). One release/acquire cluster
// barrier per step orders pushes. Gates = Whi*hhi + Wlo*hhi + Whi*hlo.

#define TT 512
#define RANKS 16
#define NT 128
#define ASTR 264            // bf16 elems per B row (528 B)

// ---- SMEM layout (from 1KB-aligned base) ----
#define PLANE_B  16896u     // 32 * 528
#define BUF_B    33792u     // hi + lo plane
#define OFF_GS   67584u     // 4 warps x 2560
#define OFF_XS   77824u     // 16 steps x 32 b fp32 = 2048
#define OFF_STG  79872u     // 2KB local stage (hi 1KB + lo 1KB)
#define SM_BYTES (81920 + 1024)

extern __shared__ __align__(16) char smem_raw[];

// ---------------- asm helpers ----------------
static __device__ __forceinline__ uint32_t smem_u32(const void* p) {
    uint32_t a;
    asm("{ .reg .u64 t; cvta.to.shared.u64 t, %1; cvt.u32.u64 %0, t; }"
        : "=r"(a) : "l"(p));
    return a;
}
static __device__ __forceinline__ void sts16(uint32_t a, uint16_t v) {
    asm volatile("st.shared.u16 [%0], %1;" :: "r"(a), "h"(v));
}
static __device__ __forceinline__ void sts32f(uint32_t a, float v) {
    asm volatile("st.shared.f32 [%0], %1;" :: "r"(a), "f"(v));
}
static __device__ __forceinline__ void sts32u(uint32_t a, uint32_t v) {
    asm volatile("st.shared.b32 [%0], %1;" :: "r"(a), "r"(v));
}
static __device__ __forceinline__ float lds32f(uint32_t a) {
    float v; asm volatile("ld.shared.f32 %0, [%1];" : "=f"(v) : "r"(a));
    return v;
}
static __device__ __forceinline__ uint32_t lds32u(uint32_t a) {
    uint32_t v; asm volatile("ld.shared.b32 %0, [%1];" : "=r"(v) : "r"(a));
    return v;
}
static __device__ __forceinline__ uint4 lds128u(uint32_t a) {
    uint4 v;
    asm volatile("ld.shared.v4.b32 {%0,%1,%2,%3}, [%4];"
                 : "=r"(v.x), "=r"(v.y), "=r"(v.z), "=r"(v.w) : "r"(a));
    return v;
}
static __device__ __forceinline__ float4 lds128f(uint32_t a) {
    float4 v;
    asm volatile("ld.shared.v4.f32 {%0,%1,%2,%3}, [%4];"
                 : "=f"(v.x), "=f"(v.y), "=f"(v.z), "=f"(v.w) : "r"(a));
    return v;
}
static __device__ __forceinline__ void ldsm4(uint32_t* r, uint32_t a) {
    asm volatile("ldmatrix.sync.aligned.m8n8.x4.shared.b16 {%0,%1,%2,%3}, [%4];"
                 : "=r"(r[0]), "=r"(r[1]), "=r"(r[2]), "=r"(r[3]) : "r"(a));
}
static __device__ __forceinline__ void mma16816(float* c, const uint32_t* a,
                                                const uint32_t* b) {
    asm volatile(
        "mma.sync.aligned.m16n8k16.row.col.f32.bf16.bf16.f32 "
        "{%0,%1,%2,%3},{%4,%5,%6,%7},{%8,%9},{%0,%1,%2,%3};"
        : "+f"(c[0]), "+f"(c[1]), "+f"(c[2]), "+f"(c[3])
        : "r"(a[0]), "r"(a[1]), "r"(a[2]), "r"(a[3]), "r"(b[0]), "r"(b[1]));
}
static __device__ __forceinline__ uint32_t mapa_sh(uint32_t a, uint32_t r) {
    uint32_t d; asm("mapa.shared::cluster.u32 %0, %1, %2;" : "=r"(d) : "r"(a), "r"(r));
    return d;
}
static __device__ __forceinline__ void st_cluster128(uint32_t a, uint4 v) {
    asm volatile("st.shared::cluster.v4.b32 [%0], {%1,%2,%3,%4};"
                 :: "r"(a), "r"(v.x), "r"(v.y), "r"(v.z), "r"(v.w) : "memory");
}
static __device__ __forceinline__ void cluster_arrive_rel() {
    asm volatile("barrier.cluster.arrive.release.aligned;" ::: "memory");
}
static __device__ __forceinline__ void cluster_wait_acq() {
    asm volatile("barrier.cluster.wait.acquire.aligned;" ::: "memory");
}
static __device__ __forceinline__ float tanh_a(float x) {
    float y; asm("tanh.approx.f32 %0, %1;" : "=f"(y) : "f"(x)); return y;
}
static __device__ __forceinline__ float sigm(float x) {
    return fmaf(0.5f, tanh_a(0.5f * x), 0.5f);
}
static __device__ __forceinline__ uint32_t pack_hi2(float2 v) {
    __nv_bfloat16 hx = __float2bfloat16(v.x);
    __nv_bfloat16 hy = __float2bfloat16(v.y);
    return ((uint32_t)__bfloat16_as_ushort(hy) << 16) |
           (uint32_t)__bfloat16_as_ushort(hx);
}
static __device__ __forceinline__ uint32_t pack_lo2(float2 v) {
    __nv_bfloat16 hx = __float2bfloat16(v.x);
    __nv_bfloat16 hy = __float2bfloat16(v.y);
    __nv_bfloat16 lx = __float2bfloat16(v.x - __bfloat162float(hx));
    __nv_bfloat16 ly = __float2bfloat16(v.y - __bfloat162float(hy));
    return ((uint32_t)__bfloat16_as_ushort(ly) << 16) |
           (uint32_t)__bfloat16_as_ushort(lx);
}
static __device__ __forceinline__ float bf16_lo_f(uint32_t v) {
    return __bfloat162float(__ushort_as_bfloat16((unsigned short)(v & 0xFFFF)));
}
static __device__ __forceinline__ float bf16_hi_f(uint32_t v) {
    return __bfloat162float(__ushort_as_bfloat16((unsigned short)(v >> 16)));
}

__global__ void __launch_bounds__(NT, 1)
lstm_kernel(const float* __restrict__ x,    const float* __restrict__ wih,
            const float* __restrict__ whh,  const float* __restrict__ bih,
            const float* __restrict__ bhh,  const float* __restrict__ wfc,
            const float* __restrict__ bfc,  float* __restrict__ out)
{
    const int t      = threadIdx.x;
    const int lane   = t & 31;
    const int w      = t >> 5;          // warp 0..3
    const int cta    = blockIdx.x;
    const int rank   = cta % RANKS;
    const int cl     = cta / RANKS;     // cluster/tile 0..15
    const int batch0 = cl * 32;
    const int unit0  = rank * 16;

    const uint32_t base = (smem_u32(smem_raw) + 1023u) & ~1023u;
    const uint32_t sGS  = base + OFF_GS;
    const uint32_t sXS  = base + OFF_XS;
    const uint32_t sSTG = base + OFF_STG;

    // ---- A fragments: W' -> registers, once. Local m row = u*4+g. ----
    // Global W_hh row for local m: (m&3)*256 + unit0 + (m>>2).
    uint32_t aHiF[16][4], aLoF[16][4];
    {
        const int r0 = 16 * w + (lane >> 2);
        const int r1 = r0 + 8;
        const float* R0 = whh + ((size_t)((r0 & 3) * 256 + unit0 + (r0 >> 2))) * 256;
        const float* R1 = whh + ((size_t)((r1 & 3) * 256 + unit0 + (r1 >> 2))) * 256;
        const int c0 = (lane & 3) * 2;
        #pragma unroll
        for (int kt = 0; kt < 16; kt++) {
            float2 v0 = __ldg((const float2*)(R0 + kt * 16 + c0));
            float2 v1 = __ldg((const float2*)(R1 + kt * 16 + c0));
            float2 v2 = __ldg((const float2*)(R0 + kt * 16 + c0 + 8));
            float2 v3 = __ldg((const float2*)(R1 + kt * 16 + c0 + 8));
            aHiF[kt][0] = pack_hi2(v0);  aLoF[kt][0] = pack_lo2(v0);
            aHiF[kt][1] = pack_hi2(v1);  aLoF[kt][1] = pack_lo2(v1);
            aHiF[kt][2] = pack_hi2(v2);  aLoF[kt][2] = pack_lo2(v2);
            aHiF[kt][3] = pack_hi2(v3);  aLoF[kt][3] = pack_lo2(v3);
        }
    }

    // ---- Per-thread activation params: u = t>>3 (0..15), b = 4(t&7)+j ----
    const int u  = t >> 3;
    const int bq = t & 7;
    float wihr[4], biasr[4];
    #pragma unroll
    for (int g = 0; g < 4; g++) {
        int r = g * 256 + unit0 + u;
        wihr[g]  = __ldg(&wih[r]);
        biasr[g] = __ldg(&bih[r]) + __ldg(&bhh[r]);
    }

    // ---- Peer SMEM base addresses (mapa once) ----
    uint32_t peerB[RANKS];
    #pragma unroll
    for (int r = 0; r < RANKS; r++) peerB[r] = mapa_sh(base, (uint32_t)r);

    // ---- Zero B buffer 0 (h(0) = 0), own CTA only ----
    for (int i = t; i < (int)(BUF_B / 4); i += NT) sts32u(base + 4u * i, 0u);
    float cc[4] = {0.f, 0.f, 0.f, 0.f};

    // ---- ldmatrix B lane offsets (R8 layout) ----
    uint32_t bOff[2];
    #pragma unroll
    for (int P = 0; P < 2; P++) {
        int nB = 16 * P + (lane & 7) + (((lane >> 4) & 1) << 3);
        int ka = (lane & 8) ? 8 : 0;
        bOff[P] = (uint32_t)((nB * ASTR + ka) * 2);
    }

    __syncthreads();
    cluster_arrive_rel();   // everyone's buf0 zeroed & visible
    cluster_wait_acq();

    int p = 0;
    for (int step = 0; step < TT; step++) {
        // ---- x chunk every 16 steps (rare; needs a block sync after) ----
        if ((step & 15) == 0) {
            int bx = t >> 2, i4 = t & 3;
            float4 v = __ldg((const float4*)&x[(size_t)(batch0 + bx) * TT + step] + i4);
            uint32_t a0 = sXS + (uint32_t)(((i4 * 4 + 0) * 32 + bx) * 4);
            sts32f(a0,        v.x);
            sts32f(a0 + 128u, v.y);
            sts32f(a0 + 256u, v.z);
            sts32f(a0 + 384u, v.w);
            __syncthreads();
        }

        // ---- MMA immediately: B is already in SMEM (pushed by peers) ----
        const uint32_t bufHi = base + (uint32_t)p * BUF_B;
        const uint32_t bufLo = bufHi + PLANE_B;
        float c0[4] = {0,0,0,0}, c1[4] = {0,0,0,0};
        float c2[4] = {0,0,0,0}, c3[4] = {0,0,0,0};
        uint32_t bh0 = bufHi + bOff[0], bh1 = bufHi + bOff[1];
        uint32_t bl0 = bufLo + bOff[0], bl1 = bufLo + bOff[1];
        #pragma unroll
        for (int kt = 0; kt < 16; kt++) {
            uint32_t bh[8], bl[8];
            ldsm4(bh, bh0);  ldsm4(bh + 4, bh1);
            ldsm4(bl, bl0);  ldsm4(bl + 4, bl1);
            bh0 += 32; bh1 += 32; bl0 += 32; bl1 += 32;
            mma16816(c0, aHiF[kt], bh);      mma16816(c1, aHiF[kt], bh + 2);
            mma16816(c2, aHiF[kt], bh + 4);  mma16816(c3, aHiF[kt], bh + 6);
            mma16816(c0, aLoF[kt], bh);      mma16816(c1, aLoF[kt], bh + 2);
            mma16816(c2, aLoF[kt], bh + 4);  mma16816(c3, aLoF[kt], bh + 6);
            mma16816(c0, aHiF[kt], bl);      mma16816(c1, aHiF[kt], bl + 2);
            mma16816(c2, aHiF[kt], bl + 4);  mma16816(c3, aHiF[kt], bl + 6);
        }

        // ---- D fragments -> warp-private gates scratch ----
        {
            uint32_t gw = sGS + (uint32_t)(w * 2560);
            int mr = lane >> 2;
            int j0 = 2 * (lane & 3);
            float* cs[4] = {c0, c1, c2, c3};
            #pragma unroll
            for (int nt = 0; nt < 4; nt++) {
                int col = nt * 8 + j0;
                sts32f(gw + (uint32_t)((col    ) * 80 + mr * 4),       cs[nt][0]);
                sts32f(gw + (uint32_t)((col + 1) * 80 + mr * 4),       cs[nt][1]);
                sts32f(gw + (uint32_t)((col    ) * 80 + (mr + 8) * 4), cs[nt][2]);
                sts32f(gw + (uint32_t)((col + 1) * 80 + (mr + 8) * 4), cs[nt][3]);
            }
        }
        __syncwarp();

        // ---- Activations (warp-local): 4 cells (u, 4bq+j) ----
        float hv[4];
        {
            uint32_t gw = sGS + (uint32_t)(w * 2560) + (uint32_t)((lane >> 3) * 16);
            #pragma unroll
            for (int j = 0; j < 4; j++) {
                int b = 4 * bq + j;
                float4 gv = lds128f(gw + (uint32_t)(b * 80));
                float xv  = lds32f(sXS + (uint32_t)(((step & 15) * 32 + b) * 4));
                float gi = gv.x + fmaf(xv, wihr[0], biasr[0]);
                float gf = gv.y + fmaf(xv, wihr[1], biasr[1]);
                float gg = gv.z + fmaf(xv, wihr[2], biasr[2]);
                float go = gv.w + fmaf(xv, wihr[3], biasr[3]);
                float c = sigm(gf) * cc[j] + sigm(gi) * tanh_a(gg);
                cc[j] = c;
                hv[j] = sigm(go) * tanh_a(c);
            }
        }

        // ---- Stage own h (bf16 hi/lo) locally: stg[plane][b][u] 2B ----
        #pragma unroll
        for (int j = 0; j < 4; j++) {
            int b = 4 * bq + j;
            __nv_bfloat16 hb = __float2bfloat16(hv[j]);
            __nv_bfloat16 lb = __float2bfloat16(hv[j] - __bfloat162float(hb));
            sts16(sSTG +         (uint32_t)(b * 32 + u * 2), __bfloat16_as_ushort(hb));
            sts16(sSTG + 1024u + (uint32_t)(b * 32 + u * 2), __bfloat16_as_ushort(lb));
        }
        __syncthreads();

        // ---- Push my 2KB to all 16 peers' buf(p^1) (16B granule per thr) ----
        {
            uint4 v = lds128u(sSTG + (uint32_t)(t * 16));
            uint32_t dsto = (uint32_t)((p ^ 1) * BUF_B)
                          + (uint32_t)((t >> 6) * PLANE_B)
                          + (uint32_t)(((t >> 1) & 31) * 528)
                          + (uint32_t)(rank * 32)
                          + (uint32_t)((t & 1) * 16);
            #pragma unroll
            for (int r = 0; r < RANKS; r++)
                st_cluster128(peerB[r] + dsto, v);
        }

        cluster_arrive_rel();   // release my pushes cluster-wide
        cluster_wait_acq();     // all peers' pushes for p^1 complete
        p ^= 1;
    }

    // ---- FC head: rank 0 reads final h from OWN buf0 SMEM ----
    if (rank == 0) {
        // final h landed in buf index TT&1 ^ ... : last push targeted p^1
        // with p = 511&1 = 1 -> buf0. p after loop = 0.
        const uint32_t fHi = base;            // buf0 hi plane
        const uint32_t fLo = base + PLANE_B;
        int b = t >> 2, seg = t & 3;          // 4 segments x 32 unit-pairs
        float s = 0.f;
        #pragma unroll 4
        for (int jj = 0; jj < 32; jj++) {
            int pr = seg * 32 + jj;           // unit pair -> units 2pr, 2pr+1
            uint32_t hi = lds32u(fHi + (uint32_t)(b * 528 + pr * 4));
            uint32_t lo = lds32u(fLo + (uint32_t)(b * 528 + pr * 4));
            float h0 = bf16_lo_f(hi) + bf16_lo_f(lo);
            float h1 = bf16_hi_f(hi) + bf16_hi_f(lo);
            s = fmaf(fmaxf(h0, 0.f), __ldg(&wfc[2 * pr]),     s);
            s = fmaf(fmaxf(h1, 0.f), __ldg(&wfc[2 * pr + 1]), s);
        }
        sts32f(sGS + (uint32_t)((b * 4 + seg) * 4), s);
        __syncthreads();
        if (t < 32) {
            float tot = __ldg(bfc);
            #pragma unroll
            for (int sg = 0; sg < 4; sg++)
                tot += lds32f(sGS + (uint32_t)((t * 4 + sg) * 4));
            out[batch0 + t] = tot;
        }
    }
    // keep cluster alive until everyone is done reading its SMEM
    cluster_arrive_rel();
    cluster_wait_acq();
}

extern "C" void kernel_launch(void* const* d_in, const int* in_sizes, int n_in,
                              void* d_out, int out_size) {
    const float* x   = (const float*)d_in[0];
    const float* wih = (const float*)d_in[1];
    const float* whh = (const float*)d_in[2];
    const float* bih = (const float*)d_in[3];
    const float* bhh = (const float*)d_in[4];
    const float* wfc = (const float*)d_in[5];
    const float* bfc = (const float*)d_in[6];
    (void)in_sizes; (void)n_in; (void)out_size;

    cudaFuncSetAttribute(lstm_kernel,
                         cudaFuncAttributeMaxDynamicSharedMemorySize, SM_BYTES);
    cudaFuncSetAttribute(lstm_kernel,
                         cudaFuncAttributeNonPortableClusterSizeAllowed, 1);

    cudaLaunchConfig_t cfg = {};
    cfg.gridDim  = {256, 1, 1};
    cfg.blockDim = {NT, 1, 1};
    cfg.dynamicSmemBytes = SM_BYTES;
    cudaLaunchAttribute at[1];
    at[0].id = cudaLaunchAttributeClusterDimension;
    at[0].val.clusterDim = {RANKS, 1, 1};
    cfg.attrs = at; cfg.numAttrs = 1;
    cudaLaunchKernelEx(&cfg, lstm_kernel, x, wih, whh, bih, bhh, wfc, bfc,
                       (float*)d_out);
}

// round 13
// speedup vs baseline: 2.0787x; 2.0787x over previous
#include <cuda_runtime.h>
#include <cuda_fp16.h>
#include <cstdint>

// BG_LSTM via warp-level HMMA, R13: fp16 2-term split (vs bf16 3-term).
// R8 topology (proven best): 16 clusters x 16 CTAs (non-portable), 128
// threads/CTA, 2 CTAs/SM. Cluster owns 32 batches; CTA rank owns 16 units
// (64 gate rows). W_hh in SMEM as TWO fp16 planes: Whi and Wlo*2048
// (W = Whi + Wlo/2048, accurate to ~2^-22). h exchanged through L2 as a
// SINGLE fp16 plane [b][u] -> staging is 8x(LDG.128+STS.128), no repack.
// Gates = Whi*h + (Wlo*h)/2048, fp32 accumulators. FC head computed from
// fp32 register h (not the fp16 exchange), reduced via global scratch.

#define TT 512
#define RANKS 16
#define NT 128
#define MROWS 64
#define ASTR 264            // fp16 elems per plane row (528 B)
#define INV2048 4.8828125e-4f

// h exchange: single fp16 plane, [buf][tile][batch][unit]
__device__ __half g_hx[2][16][32][256];
// FC partials: [tile][rank][batch]
__device__ float g_fcpart[16][16][32];

extern __shared__ __align__(16) char smem_raw[];

// ---- SMEM offsets (from 1KB-aligned base) ----
#define OFF_WLO 33792u      // Whi plane: 64*528 = 33792
#define OFF_B   67584u      // B plane: 32*528 = 16896
#define OFF_GS  84480u      // 4 warps x 2560 = 10240
#define OFF_XS  94720u      // 16 steps x 32 b fp32 = 2048
#define SM_BYTES (96768 + 1024)

// ---------------- asm helpers ----------------
static __device__ __forceinline__ uint32_t smem_u32(const void* p) {
    uint32_t a;
    asm("{ .reg .u64 t; cvta.to.shared.u64 t, %1; cvt.u32.u64 %0, t; }"
        : "=r"(a) : "l"(p));
    return a;
}
static __device__ __forceinline__ void sts128(uint32_t a, uint4 v) {
    asm volatile("st.shared.v4.b32 [%0], {%1,%2,%3,%4};"
                 :: "r"(a), "r"(v.x), "r"(v.y), "r"(v.z), "r"(v.w));
}
static __device__ __forceinline__ void sts32f(uint32_t a, float v) {
    asm volatile("st.shared.f32 [%0], %1;" :: "r"(a), "f"(v));
}
static __device__ __forceinline__ void sts32u(uint32_t a, uint32_t v) {
    asm volatile("st.shared.b32 [%0], %1;" :: "r"(a), "r"(v));
}
static __device__ __forceinline__ float lds32f(uint32_t a) {
    float v; asm volatile("ld.shared.f32 %0, [%1];" : "=f"(v) : "r"(a));
    return v;
}
static __device__ __forceinline__ float4 lds128f(uint32_t a) {
    float4 v;
    asm volatile("ld.shared.v4.f32 {%0,%1,%2,%3}, [%4];"
                 : "=f"(v.x), "=f"(v.y), "=f"(v.z), "=f"(v.w) : "r"(a));
    return v;
}
static __device__ __forceinline__ void ldsm4(uint32_t* r, uint32_t a) {
    asm volatile("ldmatrix.sync.aligned.m8n8.x4.shared.b16 {%0,%1,%2,%3}, [%4];"
                 : "=r"(r[0]), "=r"(r[1]), "=r"(r[2]), "=r"(r[3]) : "r"(a));
}
static __device__ __forceinline__ void mma16816(float* c, const uint32_t* a,
                                                const uint32_t* b) {
    asm volatile(
        "mma.sync.aligned.m16n8k16.row.col.f32.f16.f16.f32 "
        "{%0,%1,%2,%3},{%4,%5,%6,%7},{%8,%9},{%0,%1,%2,%3};"
        : "+f"(c[0]), "+f"(c[1]), "+f"(c[2]), "+f"(c[3])
        : "r"(a[0]), "r"(a[1]), "r"(a[2]), "r"(a[3]), "r"(b[0]), "r"(b[1]));
}
static __device__ __forceinline__ void cluster_arrive_rel() {
    asm volatile("barrier.cluster.arrive.release.aligned;" ::: "memory");
}
static __device__ __forceinline__ void cluster_wait_acq() {
    asm volatile("barrier.cluster.wait.acquire.aligned;" ::: "memory");
}
static __device__ __forceinline__ float tanh_a(float x) {
    float y; asm("tanh.approx.f32 %0, %1;" : "=f"(y) : "f"(x)); return y;
}
static __device__ __forceinline__ float sigm(float x) {
    return fmaf(0.5f, tanh_a(0.5f * x), 0.5f);
}

__global__ void __launch_bounds__(NT, 1)
lstm_kernel(const float* __restrict__ x,    const float* __restrict__ wih,
            const float* __restrict__ whh,  const float* __restrict__ bih,
            const float* __restrict__ bhh,  const float* __restrict__ wfc,
            const float* __restrict__ bfc,  float* __restrict__ out)
{
    const int t      = threadIdx.x;
    const int lane   = t & 31;
    const int w      = t >> 5;          // warp 0..3
    const int cta    = blockIdx.x;
    const int rank   = cta % RANKS;
    const int cl     = cta / RANKS;     // tile 0..15
    const int batch0 = cl * 32;
    const int unit0  = rank * 16;

    const uint32_t base = (smem_u32(smem_raw) + 1023u) & ~1023u;
    const uint32_t sWhi = base;
    const uint32_t sWlo = base + OFF_WLO;
    const uint32_t sB   = base + OFF_B;
    const uint32_t sGS  = base + OFF_GS;
    const uint32_t sXS  = base + OFF_XS;

    // ---- One-time: W -> fp16 planes (Whi, Wlo*2048). Row m = u*4+g. ----
    if (t < MROWS) {
        const int m = t;
        const float* wrow = whh + ((size_t)((m & 3) * 256 + unit0 + (m >> 2))) * 256;
        uint32_t ah = sWhi + (uint32_t)(m * ASTR * 2);
        uint32_t al = sWlo + (uint32_t)(m * ASTR * 2);
        #pragma unroll 8
        for (int k2 = 0; k2 < 128; k2++) {
            float2 wv = *(const float2*)(wrow + 2 * k2);
            __half hx = __float2half(wv.x);
            __half hy = __float2half(wv.y);
            __half lx = __float2half((wv.x - __half2float(hx)) * 2048.0f);
            __half ly = __float2half((wv.y - __half2float(hy)) * 2048.0f);
            uint32_t hi = ((uint32_t)__half_as_ushort(hy) << 16) |
                          (uint32_t)__half_as_ushort(hx);
            uint32_t lo = ((uint32_t)__half_as_ushort(ly) << 16) |
                          (uint32_t)__half_as_ushort(lx);
            sts32u(ah + 4u * k2, hi);
            sts32u(al + 4u * k2, lo);
        }
    }

    // ---- Per-thread activation params: u = t>>3 (0..15), b = 4(t&7)+j ----
    const int u  = t >> 3;
    const int bq = t & 7;
    float wihr[4], biasr[4];
    #pragma unroll
    for (int g = 0; g < 4; g++) {
        int r = g * 256 + unit0 + u;
        wihr[g]  = __ldg(&wih[r]);
        biasr[g] = __ldg(&bih[r]) + __ldg(&bhh[r]);
    }
    const float wfcr = __ldg(&wfc[unit0 + u]);

    // ---- Zero h buffer 0 for my tile (1/16 per CTA) ----
    {
        uint32_t* gz = (uint32_t*)&g_hx[0][cl][0][0];   // 4096 u32 per tile
        __stcg(&gz[rank * 256 + t], 0u);
        __stcg(&gz[rank * 256 + t + NT], 0u);
    }
    float cc[4] = {0.f, 0.f, 0.f, 0.f};
    float hv[4] = {0.f, 0.f, 0.f, 0.f};

    // ---- ldmatrix lane base addresses (R8 layout) ----
    const uint32_t aOff =
        (uint32_t)(((16 * w + (lane & 15)) * ASTR + ((lane >> 4) * 8)) * 2);
    uint32_t bOff[2];
    #pragma unroll
    for (int P = 0; P < 2; P++) {
        int nB = 16 * P + (lane & 7) + (((lane >> 4) & 1) << 3);
        int ka = (lane & 8) ? 8 : 0;
        bOff[P] = (uint32_t)((nB * ASTR + ka) * 2);
    }

    __syncthreads();
    cluster_arrive_rel();
    cluster_wait_acq();

    int p = 0;
    for (int step = 0; step < TT; step++) {
        // ---- Stage B plane: 8x(LDG.128 -> STS.128), layout-preserving ----
        {
            const uint4* src = (const uint4*)&g_hx[p][cl][0][0];
            #pragma unroll
            for (int i = 0; i < 8; i++) {
                int id  = t + i * NT;        // 1024 granules of 8 fp16
                int b   = id >> 5;
                int col = id & 31;
                uint4 v = __ldcg(&src[id]);
                sts128(sB + (uint32_t)(b * 528 + col * 16), v);
            }
        }
        // ---- Stage x chunk every 16 steps: xs[(s&15)*32 + b] ----
        if ((step & 15) == 0) {
            int bx = t >> 2, i4 = t & 3;
            float4 v = __ldg((const float4*)&x[(size_t)(batch0 + bx) * TT + step] + i4);
            uint32_t a0 = sXS + (uint32_t)(((i4 * 4 + 0) * 32 + bx) * 4);
            sts32f(a0,        v.x);
            sts32f(a0 + 128u, v.y);
            sts32f(a0 + 256u, v.z);
            sts32f(a0 + 384u, v.w);
        }
        __syncthreads();

        // ---- MMA: 2 terms (Whi*h, Wlo_scaled*h), 16 k-tiles ----
        float cA0[4] = {0,0,0,0}, cA1[4] = {0,0,0,0};
        float cA2[4] = {0,0,0,0}, cA3[4] = {0,0,0,0};
        float cB0[4] = {0,0,0,0}, cB1[4] = {0,0,0,0};
        float cB2[4] = {0,0,0,0}, cB3[4] = {0,0,0,0};
        uint32_t aHi = sWhi + aOff, aLo = sWlo + aOff;
        uint32_t b0 = sB + bOff[0], b1 = sB + bOff[1];
        #pragma unroll 4
        for (int kt = 0; kt < 16; kt++) {
            uint32_t ah[4], al[4], bb[8];
            ldsm4(ah, aHi);  ldsm4(al, aLo);
            ldsm4(bb, b0);   ldsm4(bb + 4, b1);
            aHi += 32; aLo += 32; b0 += 32; b1 += 32;
            mma16816(cA0, ah, bb);      mma16816(cA1, ah, bb + 2);
            mma16816(cA2, ah, bb + 4);  mma16816(cA3, ah, bb + 6);
            mma16816(cB0, al, bb);      mma16816(cB1, al, bb + 2);
            mma16816(cB2, al, bb + 4);  mma16816(cB3, al, bb + 6);
        }
        #pragma unroll
        for (int i = 0; i < 4; i++) {
            cA0[i] = fmaf(cB0[i], INV2048, cA0[i]);
            cA1[i] = fmaf(cB1[i], INV2048, cA1[i]);
            cA2[i] = fmaf(cB2[i], INV2048, cA2[i]);
            cA3[i] = fmaf(cB3[i], INV2048, cA3[i]);
        }

        // ---- D fragments -> warp-private gates scratch ----
        {
            uint32_t gw = sGS + (uint32_t)(w * 2560);
            int mr = lane >> 2;            // m_local rows mr, mr+8
            int j0 = 2 * (lane & 3);
            float* cs[4] = {cA0, cA1, cA2, cA3};
            #pragma unroll
            for (int nt = 0; nt < 4; nt++) {
                int col = nt * 8 + j0;
                sts32f(gw + (uint32_t)((col    ) * 80 + mr * 4),       cs[nt][0]);
                sts32f(gw + (uint32_t)((col + 1) * 80 + mr * 4),       cs[nt][1]);
                sts32f(gw + (uint32_t)((col    ) * 80 + (mr + 8) * 4), cs[nt][2]);
                sts32f(gw + (uint32_t)((col + 1) * 80 + (mr + 8) * 4), cs[nt][3]);
            }
        }
        __syncwarp();

        // ---- Activations (warp-local): 4 cells (u, 4bq+j) ----
        {
            uint32_t gw = sGS + (uint32_t)(w * 2560) + (uint32_t)((lane >> 3) * 16);
            #pragma unroll
            for (int j = 0; j < 4; j++) {
                int b = 4 * bq + j;
                float4 gv = lds128f(gw + (uint32_t)(b * 80));
                float xv  = lds32f(sXS + (uint32_t)(((step & 15) * 32 + b) * 4));
                float gi = gv.x + fmaf(xv, wihr[0], biasr[0]);
                float gf = gv.y + fmaf(xv, wihr[1], biasr[1]);
                float gg = gv.z + fmaf(xv, wihr[2], biasr[2]);
                float go = gv.w + fmaf(xv, wihr[3], biasr[3]);
                float c = sigm(gf) * cc[j] + sigm(gi) * tanh_a(gg);
                cc[j] = c;
                hv[j] = sigm(go) * tanh_a(c);
                // store fp16 h to exchange buffer
                g_hx[p ^ 1][cl][b][unit0 + u] = __float2half(hv[j]);
            }
        }

        cluster_arrive_rel();
        cluster_wait_acq();
        p ^= 1;
    }

    // ---- FC head from fp32 register h ----
    // Per-thread: s_j = relu(hv[j]) * wfc[unit]; reduce over u in SMEM.
    #pragma unroll
    for (int j = 0; j < 4; j++) {
        int b = 4 * bq + j;
        sts32f(sGS + (uint32_t)((b * 16 + u) * 4), fmaxf(hv[j], 0.f) * wfcr);
    }
    __syncthreads();
    if (t < 32) {
        float s = 0.f;
        #pragma unroll
        for (int uu = 0; uu < 16; uu++)
            s += lds32f(sGS + (uint32_t)((t * 16 + uu) * 4));
        g_fcpart[cl][rank][t] = s;
    }
    cluster_arrive_rel();    // release partials cluster-wide
    cluster_wait_acq();
    if (rank == 0 && t < 32) {
        float tot = __ldg(bfc);
        #pragma unroll
        for (int r = 0; r < RANKS; r++)
            tot += g_fcpart[cl][r][t];
        out[batch0 + t] = tot;
    }
}

extern "C" void kernel_launch(void* const* d_in, const int* in_sizes, int n_in,
                              void* d_out, int out_size) {
    const float* x   = (const float*)d_in[0];
    const float* wih = (const float*)d_in[1];
    const float* whh = (const float*)d_in[2];
    const float* bih = (const float*)d_in[3];
    const float* bhh = (const float*)d_in[4];
    const float* wfc = (const float*)d_in[5];
    const float* bfc = (const float*)d_in[6];
    (void)in_sizes; (void)n_in; (void)out_size;

    cudaFuncSetAttribute(lstm_kernel,
                         cudaFuncAttributeMaxDynamicSharedMemorySize, SM_BYTES);
    cudaFuncSetAttribute(lstm_kernel,
                         cudaFuncAttributeNonPortableClusterSizeAllowed, 1);

    cudaLaunchConfig_t cfg = {};
    cfg.gridDim  = {256, 1, 1};
    cfg.blockDim = {NT, 1, 1};
    cfg.dynamicSmemBytes = SM_BYTES;
    cudaLaunchAttribute at[1];
    at[0].id = cudaLaunchAttributeClusterDimension;
    at[0].val.clusterDim = {RANKS, 1, 1};
    cfg.attrs = at; cfg.numAttrs = 1;
    cudaLaunchKernelEx(&cfg, lstm_kernel, x, wih, whh, bih, bhh, wfc, bfc,
                       (float*)d_out);
}

// round 14
// speedup vs baseline: 3.3000x; 1.5875x over previous
#include <cuda_runtime.h>
#include <cuda_fp16.h>
#include <cstdint>

// BG_LSTM via warp-level HMMA, R14: pure fp16 single-term MMA.
// R8/R13 topology (proven): 16 clusters x 16 CTAs (non-portable), 128
// threads/CTA, 2 CTAs/SM. Cluster owns 32 batches; CTA rank owns 16 units
// (64 gate rows). W_hh in SMEM as ONE fp16 plane; h exchanged through L2
// as a single fp16 plane [b][u] (staging = 8x(LDG.128+STS.128), no
// repack). Gates = W*h in fp16 with fp32 accumulators (64 HMMA/warp/step).
// Per-step fp16 quantization of W and h each contribute ~2.6e-5 end-to-end
// rel_err (measured scaling, R13) -> expected ~5-8e-5, gate is 1e-3.
// FC head computed from fp32 register h, reduced via global scratch.

#define TT 512
#define RANKS 16
#define NT 128
#define MROWS 64
#define ASTR 264            // fp16 elems per plane row (528 B)

// h exchange: single fp16 plane, [buf][tile][batch][unit]
__device__ __half g_hx[2][16][32][256];
// FC partials: [tile][rank][batch]
__device__ float g_fcpart[16][16][32];

extern __shared__ __align__(16) char smem_raw[];

// ---- SMEM offsets (from 1KB-aligned base) ----
#define OFF_B   33792u      // W plane: 64*528 = 33792; B plane: 32*528
#define OFF_GS  50688u      // 4 warps x 2560 = 10240
#define OFF_XS  60928u      // 16 steps x 32 b fp32 = 2048
#define SM_BYTES (62976 + 1024)

// ---------------- asm helpers ----------------
static __device__ __forceinline__ uint32_t smem_u32(const void* p) {
    uint32_t a;
    asm("{ .reg .u64 t; cvta.to.shared.u64 t, %1; cvt.u32.u64 %0, t; }"
        : "=r"(a) : "l"(p));
    return a;
}
static __device__ __forceinline__ void sts128(uint32_t a, uint4 v) {
    asm volatile("st.shared.v4.b32 [%0], {%1,%2,%3,%4};"
                 :: "r"(a), "r"(v.x), "r"(v.y), "r"(v.z), "r"(v.w));
}
static __device__ __forceinline__ void sts32f(uint32_t a, float v) {
    asm volatile("st.shared.f32 [%0], %1;" :: "r"(a), "f"(v));
}
static __device__ __forceinline__ void sts32u(uint32_t a, uint32_t v) {
    asm volatile("st.shared.b32 [%0], %1;" :: "r"(a), "r"(v));
}
static __device__ __forceinline__ float lds32f(uint32_t a) {
    float v; asm volatile("ld.shared.f32 %0, [%1];" : "=f"(v) : "r"(a));
    return v;
}
static __device__ __forceinline__ float4 lds128f(uint32_t a) {
    float4 v;
    asm volatile("ld.shared.v4.f32 {%0,%1,%2,%3}, [%4];"
                 : "=f"(v.x), "=f"(v.y), "=f"(v.z), "=f"(v.w) : "r"(a));
    return v;
}
static __device__ __forceinline__ void ldsm4(uint32_t* r, uint32_t a) {
    asm volatile("ldmatrix.sync.aligned.m8n8.x4.shared.b16 {%0,%1,%2,%3}, [%4];"
                 : "=r"(r[0]), "=r"(r[1]), "=r"(r[2]), "=r"(r[3]) : "r"(a));
}
static __device__ __forceinline__ void mma16816(float* c, const uint32_t* a,
                                                const uint32_t* b) {
    asm volatile(
        "mma.sync.aligned.m16n8k16.row.col.f32.f16.f16.f32 "
        "{%0,%1,%2,%3},{%4,%5,%6,%7},{%8,%9},{%0,%1,%2,%3};"
        : "+f"(c[0]), "+f"(c[1]), "+f"(c[2]), "+f"(c[3])
        : "r"(a[0]), "r"(a[1]), "r"(a[2]), "r"(a[3]), "r"(b[0]), "r"(b[1]));
}
static __device__ __forceinline__ void cluster_arrive_rel() {
    asm volatile("barrier.cluster.arrive.release.aligned;" ::: "memory");
}
static __device__ __forceinline__ void cluster_wait_acq() {
    asm volatile("barrier.cluster.wait.acquire.aligned;" ::: "memory");
}
static __device__ __forceinline__ float tanh_a(float x) {
    float y; asm("tanh.approx.f32 %0, %1;" : "=f"(y) : "f"(x)); return y;
}
static __device__ __forceinline__ float sigm(float x) {
    return fmaf(0.5f, tanh_a(0.5f * x), 0.5f);
}

__global__ void __launch_bounds__(NT, 1)
lstm_kernel(const float* __restrict__ x,    const float* __restrict__ wih,
            const float* __restrict__ whh,  const float* __restrict__ bih,
            const float* __restrict__ bhh,  const float* __restrict__ wfc,
            const float* __restrict__ bfc,  float* __restrict__ out)
{
    const int t      = threadIdx.x;
    const int lane   = t & 31;
    const int w      = t >> 5;          // warp 0..3
    const int cta    = blockIdx.x;
    const int rank   = cta % RANKS;
    const int cl     = cta / RANKS;     // tile 0..15
    const int batch0 = cl * 32;
    const int unit0  = rank * 16;

    const uint32_t base = (smem_u32(smem_raw) + 1023u) & ~1023u;
    const uint32_t sW   = base;
    const uint32_t sB   = base + OFF_B;
    const uint32_t sGS  = base + OFF_GS;
    const uint32_t sXS  = base + OFF_XS;

    // ---- One-time: W -> single fp16 plane. Row m = u*4+g (u local). ----
    if (t < MROWS) {
        const int m = t;
        const float* wrow = whh + ((size_t)((m & 3) * 256 + unit0 + (m >> 2))) * 256;
        uint32_t aw = sW + (uint32_t)(m * ASTR * 2);
        #pragma unroll 8
        for (int k2 = 0; k2 < 128; k2++) {
            float2 wv = *(const float2*)(wrow + 2 * k2);
            uint32_t hi = ((uint32_t)__half_as_ushort(__float2half(wv.y)) << 16) |
                          (uint32_t)__half_as_ushort(__float2half(wv.x));
            sts32u(aw + 4u * k2, hi);
        }
    }

    // ---- Per-thread activation params: u = t>>3 (0..15), b = 4(t&7)+j ----
    const int u  = t >> 3;
    const int bq = t & 7;
    float wihr[4], biasr[4];
    #pragma unroll
    for (int g = 0; g < 4; g++) {
        int r = g * 256 + unit0 + u;
        wihr[g]  = __ldg(&wih[r]);
        biasr[g] = __ldg(&bih[r]) + __ldg(&bhh[r]);
    }
    const float wfcr = __ldg(&wfc[unit0 + u]);

    // ---- Zero h buffer 0 for my tile (1/16 per CTA) ----
    {
        uint32_t* gz = (uint32_t*)&g_hx[0][cl][0][0];   // 4096 u32 per tile
        __stcg(&gz[rank * 256 + t], 0u);
        __stcg(&gz[rank * 256 + t + NT], 0u);
    }
    float cc[4] = {0.f, 0.f, 0.f, 0.f};
    float hv[4] = {0.f, 0.f, 0.f, 0.f};

    // ---- ldmatrix lane base addresses (R8 layout) ----
    const uint32_t aOff =
        (uint32_t)(((16 * w + (lane & 15)) * ASTR + ((lane >> 4) * 8)) * 2);
    uint32_t bOff[2];
    #pragma unroll
    for (int P = 0; P < 2; P++) {
        int nB = 16 * P + (lane & 7) + (((lane >> 4) & 1) << 3);
        int ka = (lane & 8) ? 8 : 0;
        bOff[P] = (uint32_t)((nB * ASTR + ka) * 2);
    }

    __syncthreads();
    cluster_arrive_rel();
    cluster_wait_acq();

    int p = 0;
    for (int step = 0; step < TT; step++) {
        // ---- Stage B plane: 8x(LDG.128 -> STS.128), layout-preserving ----
        {
            const uint4* src = (const uint4*)&g_hx[p][cl][0][0];
            #pragma unroll
            for (int i = 0; i < 8; i++) {
                int id  = t + i * NT;        // 1024 granules of 8 fp16
                int b   = id >> 5;
                int col = id & 31;
                uint4 v = __ldcg(&src[id]);
                sts128(sB + (uint32_t)(b * 528 + col * 16), v);
            }
        }
        // ---- Stage x chunk every 16 steps: xs[(s&15)*32 + b] ----
        if ((step & 15) == 0) {
            int bx = t >> 2, i4 = t & 3;
            float4 v = __ldg((const float4*)&x[(size_t)(batch0 + bx) * TT + step] + i4);
            uint32_t a0 = sXS + (uint32_t)(((i4 * 4 + 0) * 32 + bx) * 4);
            sts32f(a0,        v.x);
            sts32f(a0 + 128u, v.y);
            sts32f(a0 + 256u, v.z);
            sts32f(a0 + 384u, v.w);
        }
        __syncthreads();

        // ---- MMA: single term W*h, 16 k-tiles ----
        float c0[4] = {0,0,0,0}, c1[4] = {0,0,0,0};
        float c2[4] = {0,0,0,0}, c3[4] = {0,0,0,0};
        uint32_t aW = sW + aOff;
        uint32_t b0 = sB + bOff[0], b1 = sB + bOff[1];
        #pragma unroll 8
        for (int kt = 0; kt < 16; kt++) {
            uint32_t ah[4], bb[8];
            ldsm4(ah, aW);
            ldsm4(bb, b0);   ldsm4(bb + 4, b1);
            aW += 32; b0 += 32; b1 += 32;
            mma16816(c0, ah, bb);      mma16816(c1, ah, bb + 2);
            mma16816(c2, ah, bb + 4);  mma16816(c3, ah, bb + 6);
        }

        // ---- D fragments -> warp-private gates scratch ----
        {
            uint32_t gw = sGS + (uint32_t)(w * 2560);
            int mr = lane >> 2;            // m_local rows mr, mr+8
            int j0 = 2 * (lane & 3);
            float* cs[4] = {c0, c1, c2, c3};
            #pragma unroll
            for (int nt = 0; nt < 4; nt++) {
                int col = nt * 8 + j0;
                sts32f(gw + (uint32_t)((col    ) * 80 + mr * 4),       cs[nt][0]);
                sts32f(gw + (uint32_t)((col + 1) * 80 + mr * 4),       cs[nt][1]);
                sts32f(gw + (uint32_t)((col    ) * 80 + (mr + 8) * 4), cs[nt][2]);
                sts32f(gw + (uint32_t)((col + 1) * 80 + (mr + 8) * 4), cs[nt][3]);
            }
        }
        __syncwarp();

        // ---- Activations (warp-local): 4 cells (u, 4bq+j) ----
        {
            uint32_t gw = sGS + (uint32_t)(w * 2560) + (uint32_t)((lane >> 3) * 16);
            #pragma unroll
            for (int j = 0; j < 4; j++) {
                int b = 4 * bq + j;
                float4 gv = lds128f(gw + (uint32_t)(b * 80));
                float xv  = lds32f(sXS + (uint32_t)(((step & 15) * 32 + b) * 4));
                float gi = gv.x + fmaf(xv, wihr[0], biasr[0]);
                float gf = gv.y + fmaf(xv, wihr[1], biasr[1]);
                float gg = gv.z + fmaf(xv, wihr[2], biasr[2]);
                float go = gv.w + fmaf(xv, wihr[3], biasr[3]);
                float c = sigm(gf) * cc[j] + sigm(gi) * tanh_a(gg);
                cc[j] = c;
                hv[j] = sigm(go) * tanh_a(c);
                g_hx[p ^ 1][cl][b][unit0 + u] = __float2half(hv[j]);
            }
        }

        cluster_arrive_rel();
        cluster_wait_acq();
        p ^= 1;
    }

    // ---- FC head from fp32 register h ----
    #pragma unroll
    for (int j = 0; j < 4; j++) {
        int b = 4 * bq + j;
        sts32f(sGS + (uint32_t)((b * 16 + u) * 4), fmaxf(hv[j], 0.f) * wfcr);
    }
    __syncthreads();
    if (t < 32) {
        float s = 0.f;
        #pragma unroll
        for (int uu = 0; uu < 16; uu++)
            s += lds32f(sGS + (uint32_t)((t * 16 + uu) * 4));
        g_fcpart[cl][rank][t] = s;
    }
    cluster_arrive_rel();    // release partials cluster-wide
    cluster_wait_acq();
    if (rank == 0 && t < 32) {
        float tot = __ldg(bfc);
        #pragma unroll
        for (int r = 0; r < RANKS; r++)
            tot += g_fcpart[cl][r][t];
        out[batch0 + t] = tot;
    }
}

extern "C" void kernel_launch(void* const* d_in, const int* in_sizes, int n_in,
                              void* d_out, int out_size) {
    const float* x   = (const float*)d_in[0];
    const float* wih = (const float*)d_in[1];
    const float* whh = (const float*)d_in[2];
    const float* bih = (const float*)d_in[3];
    const float* bhh = (const float*)d_in[4];
    const float* wfc = (const float*)d_in[5];
    const float* bfc = (const float*)d_in[6];
    (void)in_sizes; (void)n_in; (void)out_size;

    cudaFuncSetAttribute(lstm_kernel,
                         cudaFuncAttributeMaxDynamicSharedMemorySize, SM_BYTES);
    cudaFuncSetAttribute(lstm_kernel,
                         cudaFuncAttributeNonPortableClusterSizeAllowed, 1);

    cudaLaunchConfig_t cfg = {};
    cfg.gridDim  = {256, 1, 1};
    cfg.blockDim = {NT, 1, 1};
    cfg.dynamicSmemBytes = SM_BYTES;
    cudaLaunchAttribute at[1];
    at[0].id = cudaLaunchAttributeClusterDimension;
    at[0].val.clusterDim = {RANKS, 1, 1};
    cfg.attrs = at; cfg.numAttrs = 1;
    cudaLaunchKernelEx(&cfg, lstm_kernel, x, wih, whh, bih, bhh, wfc, bfc,
                       (float*)d_out);
}